// round 1
// baseline (speedup 1.0000x reference)
#include <cuda_runtime.h>
#include <cstdint>

#define EE   2048
#define CC   64
#define NTOK 18432
#define FF   18
#define PPP  1024

typedef unsigned long long u64;

// Scratch (allocation-free rule: __device__ globals)
__device__ float g_part[16 * CC * EE];   // split-K partials (8 MB)
__device__ float g_T1[CC * EE];          // Wmp @ Wo
__device__ float g_M[CC * EE];           // 0.75 * Wmp @ Wo @ Wv
__device__ float g_u[EE];                // bv @ Wo^T + bo
__device__ float g_beta[CC];

__device__ __forceinline__ void ffma2(u64& d, u64 a, u64 b) {
    asm("fma.rn.f32x2 %0, %1, %2, %0;" : "+l"(d) : "l"(a), "l"(b));
}
__device__ __forceinline__ float2 unpack2(u64 v) {
    float2 r; asm("mov.b64 {%0,%1}, %2;" : "=f"(r.x), "=f"(r.y) : "l"(v)); return r;
}
__device__ __forceinline__ unsigned smem_u32(const void* p) {
    return (unsigned)__cvta_generic_to_shared(p);
}
__device__ __forceinline__ void cp16(unsigned s, const void* g) {
    asm volatile("cp.async.ca.shared.global [%0], [%1], 16;" :: "r"(s), "l"(g));
}
__device__ __forceinline__ void cp_commit() { asm volatile("cp.async.commit_group;"); }
__device__ __forceinline__ void cp_wait0()  { asm volatile("cp.async.wait_group 0;"); }

// ---------------------------------------------------------------------------
// Precompute NN-GEMM with split-K:  D[c, j] = sum_k A[c,k] * B[k,j]
// A: 64 x 2048 (k-contig rows), B: 2048 x 2048 (j-contig rows)
// grid = (16 col-tiles of 128, 16 k-chunks of 128); writes g_part[chunk][c][j]
// ---------------------------------------------------------------------------
__global__ void __launch_bounds__(256, 1)
gemm_nn_part(const float* __restrict__ Ain, const float* __restrict__ B, int useT1)
{
    const float* A = useT1 ? g_T1 : Ain;
    __shared__ __align__(16) float As2[2][8 * 128];  // [k2][c] pair-interleaved
    __shared__ __align__(16) float Bs2[2][8 * 256];  // [k2][j] pair-interleaved

    const int tid = threadIdx.x;
    const int tx = tid & 15;            // -> c = tx + 16*jj
    const int ty = tid >> 4;            // -> j = ty + 16*i
    const int j0 = blockIdx.x * 128;
    const int kc = blockIdx.y * 128;

    const int amk = tid & 15, amc = tid >> 4;          // A loader: k, c-base
    const int bkk = tid >> 4, bcol = (tid & 15) * 8;   // B loader: k-row, j-base

    float ar[4], br[8];
    {
        const int kb = kc;
#pragma unroll
        for (int q = 0; q < 4; ++q) ar[q] = A[(size_t)(amc + 16 * q) * EE + kb + amk];
        float4 v0 = *(const float4*)&B[(size_t)(kb + bkk) * EE + j0 + bcol];
        float4 v1 = *(const float4*)&B[(size_t)(kb + bkk) * EE + j0 + bcol + 4];
        br[0]=v0.x; br[1]=v0.y; br[2]=v0.z; br[3]=v0.w;
        br[4]=v1.x; br[5]=v1.y; br[6]=v1.z; br[7]=v1.w;
    }

    u64 acc[8][4];
#pragma unroll
    for (int i = 0; i < 8; ++i)
#pragma unroll
        for (int j = 0; j < 4; ++j) acc[i][j] = 0ull;

    for (int t = 0; t < 8; ++t) {
        const int buf = t & 1;
#pragma unroll
        for (int q = 0; q < 4; ++q)
            As2[buf][(amk >> 1) * 128 + 2 * (amc + 16 * q) + (amk & 1)] = ar[q];
#pragma unroll
        for (int u = 0; u < 8; ++u)
            Bs2[buf][(bkk >> 1) * 256 + 2 * (bcol + u) + (bkk & 1)] = br[u];
        __syncthreads();

        if (t + 1 < 8) {
            const int kb = kc + (t + 1) * 16;
#pragma unroll
            for (int q = 0; q < 4; ++q) ar[q] = A[(size_t)(amc + 16 * q) * EE + kb + amk];
            float4 v0 = *(const float4*)&B[(size_t)(kb + bkk) * EE + j0 + bcol];
            float4 v1 = *(const float4*)&B[(size_t)(kb + bkk) * EE + j0 + bcol + 4];
            br[0]=v0.x; br[1]=v0.y; br[2]=v0.z; br[3]=v0.w;
            br[4]=v1.x; br[5]=v1.y; br[6]=v1.z; br[7]=v1.w;
        }

#pragma unroll
        for (int k2 = 0; k2 < 8; ++k2) {
            u64 a2[8], b2[4];
#pragma unroll
            for (int i = 0; i < 8; ++i)
                a2[i] = *(const u64*)&Bs2[buf][k2 * 256 + 2 * (ty + 16 * i)];
#pragma unroll
            for (int j = 0; j < 4; ++j)
                b2[j] = *(const u64*)&As2[buf][k2 * 128 + 2 * (tx + 16 * j)];
#pragma unroll
            for (int i = 0; i < 8; ++i)
#pragma unroll
                for (int j = 0; j < 4; ++j)
                    ffma2(acc[i][j], a2[i], b2[j]);
        }
        __syncthreads();
    }

#pragma unroll
    for (int i = 0; i < 8; ++i) {
        const int jg = j0 + ty + 16 * i;
#pragma unroll
        for (int jj = 0; jj < 4; ++jj) {
            const int c = tx + 16 * jj;
            float2 v = unpack2(acc[i][jj]);
            g_part[((size_t)blockIdx.y * CC + c) * EE + jg] = v.x + v.y;
        }
    }
}

__global__ void reduce16(float scale, int which)
{
    const int i = blockIdx.x * 256 + threadIdx.x;   // 0 .. 131071
    float s = 0.f;
#pragma unroll
    for (int q = 0; q < 16; ++q) s += g_part[(size_t)q * (CC * EE) + i];
    (which ? g_M : g_T1)[i] = s * scale;
}

// u[i] = sum_j bv[j]*Wo[i,j] + bo[i]
__global__ void k_u(const float* __restrict__ bv, const float* __restrict__ Wo,
                    const float* __restrict__ bo)
{
    const int w = (blockIdx.x * 256 + threadIdx.x) >> 5;  // 2048 warps
    const int lane = threadIdx.x & 31;
    const float* row = Wo + (size_t)w * EE;
    float s = 0.f;
    for (int j = lane; j < EE; j += 32) s += bv[j] * row[j];
#pragma unroll
    for (int o = 16; o; o >>= 1) s += __shfl_xor_sync(0xffffffffu, s, o);
    if (lane == 0) g_u[w] = s + bo[w];
}

// beta[c] = 0.75 * sum_i u[i]*Wmp[c,i] + bmp[c]
__global__ void k_beta(const float* __restrict__ Wmp, const float* __restrict__ bmp)
{
    const int c = blockIdx.x;
    const int lane = threadIdx.x;
    const float* row = Wmp + (size_t)c * EE;
    float s = 0.f;
    for (int i = lane; i < EE; i += 32) s += g_u[i] * row[i];
#pragma unroll
    for (int o = 16; o; o >>= 1) s += __shfl_xor_sync(0xffffffffu, s, o);
    if (lane == 0) g_beta[c] = 0.75f * s + bmp[c];
}

// ---------------------------------------------------------------------------
// Main GEMM (NT): out_tok[n, c] = sum_k x[n,k] * M[c,k] + beta[c]
// Output permuted: n = t*P + p  -->  out[p*F*C + t*C + c]
// grid = 144 blocks of 128 tokens; cp.async double-buffered X tiles,
// register-staged M tiles; f32x2 FMA paired over K.
// ---------------------------------------------------------------------------
__global__ void __launch_bounds__(256, 1)
main_gemm(const float* __restrict__ x, float* __restrict__ out)
{
    __shared__ __align__(16) float Xs[2][128 * 16];  // [n][k] direct copy
    __shared__ __align__(16) float Ms[2][8 * 128];   // [k2][c] pair-interleaved

    const int tid = threadIdx.x;
    const int tx = tid & 15;     // -> c = tx + 16*j
    const int ty = tid >> 4;     // -> n = n0 + ty + 16*i
    const int n0 = blockIdx.x * 128;

    const int mk = tid & 15;     // M loader: k within tile
    const int mc = tid >> 4;     // M loader: c base (c = mc + 16q)

    u64 acc[8][4];
#pragma unroll
    for (int i = 0; i < 8; ++i)
#pragma unroll
        for (int j = 0; j < 4; ++j) acc[i][j] = 0ull;

    float mreg[4];
    {   // prefetch tile 0
#pragma unroll
        for (int q = 0; q < 2; ++q) {
            const int id = tid + 256 * q;
            const int n = id >> 2, ch = id & 3;
            cp16(smem_u32(&Xs[0][n * 16 + ch * 4]),
                 x + (size_t)(n0 + n) * EE + ch * 4);
        }
        cp_commit();
#pragma unroll
        for (int q = 0; q < 4; ++q)
            mreg[q] = g_M[(size_t)(mc + 16 * q) * EE + mk];
    }

    for (int t = 0; t < EE / 16; ++t) {
        const int buf = t & 1;
        cp_wait0();
#pragma unroll
        for (int q = 0; q < 4; ++q)
            Ms[buf][(mk >> 1) * 128 + 2 * (mc + 16 * q) + (mk & 1)] = mreg[q];
        __syncthreads();

        if (t + 1 < EE / 16) {
            const int k0 = (t + 1) * 16;
            const int nb = buf ^ 1;
#pragma unroll
            for (int q = 0; q < 2; ++q) {
                const int id = tid + 256 * q;
                const int n = id >> 2, ch = id & 3;
                cp16(smem_u32(&Xs[nb][n * 16 + ch * 4]),
                     x + (size_t)(n0 + n) * EE + k0 + ch * 4);
            }
            cp_commit();
#pragma unroll
            for (int q = 0; q < 4; ++q)
                mreg[q] = g_M[(size_t)(mc + 16 * q) * EE + k0 + mk];
        }

#pragma unroll
        for (int k2 = 0; k2 < 8; ++k2) {
            u64 a2[8], b2[4];
#pragma unroll
            for (int i = 0; i < 8; ++i)
                a2[i] = *(const u64*)&Xs[buf][(ty + 16 * i) * 16 + 2 * k2];
#pragma unroll
            for (int j = 0; j < 4; ++j)
                b2[j] = *(const u64*)&Ms[buf][k2 * 128 + 2 * (tx + 16 * j)];
#pragma unroll
            for (int i = 0; i < 8; ++i)
#pragma unroll
                for (int j = 0; j < 4; ++j)
                    ffma2(acc[i][j], a2[i], b2[j]);
        }
    }

    // Epilogue: permuted store [F,P] -> [P,F], add beta
#pragma unroll
    for (int i = 0; i < 8; ++i) {
        const int n = n0 + ty + 16 * i;
        const int tt = n >> 10;       // frame index (P = 1024)
        const int p = n & 1023;       // partition index
        float* ob = out + (size_t)p * (FF * CC) + tt * CC;
#pragma unroll
        for (int j = 0; j < 4; ++j) {
            const int c = tx + 16 * j;
            float2 v = unpack2(acc[i][j]);
            ob[c] = v.x + v.y + g_beta[c];
        }
    }
}

// ---------------------------------------------------------------------------
extern "C" void kernel_launch(void* const* d_in, const int* in_sizes, int n_in,
                              void* d_out, int out_size)
{
    (void)in_sizes; (void)n_in; (void)out_size;
    const float* emb = (const float*)d_in[0];
    const float* Wv  = (const float*)d_in[3];
    const float* bv  = (const float*)d_in[6];
    const float* Wo  = (const float*)d_in[7];
    const float* bo  = (const float*)d_in[8];
    const float* Wmp = (const float*)d_in[9];
    const float* bmp = (const float*)d_in[10];
    float* out = (float*)d_out;

    // Fold weights: T1 = Wmp @ Wo ; M = 0.75 * T1 @ Wv
    gemm_nn_part<<<dim3(16, 16), 256>>>(Wmp, Wo, 0);
    reduce16<<<512, 256>>>(1.0f, 0);
    gemm_nn_part<<<dim3(16, 16), 256>>>(nullptr, Wv, 1);
    reduce16<<<512, 256>>>(0.75f, 1);

    // Fold biases: beta = 0.75*(bv@Wo^T + bo)@Wmp^T + bmp
    k_u<<<256, 256>>>(bv, Wo, bo);
    k_beta<<<64, 32>>>(Wmp, bmp);

    // Main GEMM + permuted epilogue
    main_gemm<<<144, 256>>>(emb, out);
}

// round 4
// speedup vs baseline: 1.3514x; 1.3514x over previous
#include <cuda_runtime.h>
#include <cuda_bf16.h>
#include <cstdint>

#define EE   2048
#define CC   64
#define FF   18
#define NSTG 32      // K stages of 64
#define KS   64

typedef unsigned long long u64;
typedef unsigned int u32;

// Scratch (__device__ globals: allocation-free rule)
__device__ float g_part[16 * CC * EE];                    // split-K partials (8 MB)
__device__ float g_T1[CC * EE];                           // Wmp @ Wo
__device__ float g_u[EE];                                 // bv @ Wo^T + bo
__device__ __align__(16) float g_beta[CC];
__device__ __align__(16) unsigned char g_Bh[CC * EE * 2]; // M hi, pre-swizzled per-stage tiles
__device__ __align__(16) unsigned char g_Bl[CC * EE * 2]; // M lo, pre-swizzled per-stage tiles

// ---------------- helpers ----------------
__device__ __forceinline__ void ffma2(u64& d, u64 a, u64 b) {
    asm("fma.rn.f32x2 %0, %1, %2, %0;" : "+l"(d) : "l"(a), "l"(b));
}
__device__ __forceinline__ float2 unpack2(u64 v) {
    float2 r; asm("mov.b64 {%0,%1}, %2;" : "=f"(r.x), "=f"(r.y) : "l"(v)); return r;
}
__device__ __forceinline__ unsigned smem_u32(const void* p) {
    return (unsigned)__cvta_generic_to_shared(p);
}
__device__ __forceinline__ void cp16(unsigned s, const void* g) {
    asm volatile("cp.async.ca.shared.global [%0], [%1], 16;" :: "r"(s), "l"(g));
}
__device__ __forceinline__ void cp_commit() { asm volatile("cp.async.commit_group;"); }
__device__ __forceinline__ void cp_wait0()  { asm volatile("cp.async.wait_group 0;"); }
__device__ __forceinline__ void sts64(u32 a, u32 lo, u32 hi) {
    asm volatile("st.shared.v2.u32 [%0], {%1,%2};" :: "r"(a), "r"(lo), "r"(hi));
}
__device__ __forceinline__ void ldsm4(u32& r0, u32& r1, u32& r2, u32& r3, u32 a) {
    asm volatile("ldmatrix.sync.aligned.m8n8.x4.shared.b16 {%0,%1,%2,%3}, [%4];"
                 : "=r"(r0), "=r"(r1), "=r"(r2), "=r"(r3) : "r"(a));
}
__device__ __forceinline__ void mma16816(float* c, u32 a0, u32 a1, u32 a2, u32 a3,
                                         u32 b0, u32 b1) {
    asm volatile("mma.sync.aligned.m16n8k16.row.col.f32.bf16.bf16.f32 "
                 "{%0,%1,%2,%3}, {%4,%5,%6,%7}, {%8,%9}, {%0,%1,%2,%3};"
                 : "+f"(c[0]), "+f"(c[1]), "+f"(c[2]), "+f"(c[3])
                 : "r"(a0), "r"(a1), "r"(a2), "r"(a3), "r"(b0), "r"(b1));
}
__device__ __forceinline__ u32 swz(u32 off) { return off ^ ((off >> 3) & 0x70u); }

// ---------------------------------------------------------------------------
// Precompute NN-GEMM with split-K:  D[c, j] = sum_k A[c,k] * B[k,j]
// ---------------------------------------------------------------------------
__global__ void __launch_bounds__(256, 1)
gemm_nn_part(const float* __restrict__ Ain, const float* __restrict__ B, int useT1)
{
    const float* A = useT1 ? g_T1 : Ain;
    __shared__ __align__(16) float As2[2][8 * 128];
    __shared__ __align__(16) float Bs2[2][8 * 256];

    const int tid = threadIdx.x;
    const int tx = tid & 15;
    const int ty = tid >> 4;
    const int j0 = blockIdx.x * 128;
    const int kc = blockIdx.y * 128;

    const int amk = tid & 15, amc = tid >> 4;
    const int bkk = tid >> 4, bcol = (tid & 15) * 8;

    float ar[4], br[8];
    {
        const int kb = kc;
#pragma unroll
        for (int q = 0; q < 4; ++q) ar[q] = A[(size_t)(amc + 16 * q) * EE + kb + amk];
        float4 v0 = *(const float4*)&B[(size_t)(kb + bkk) * EE + j0 + bcol];
        float4 v1 = *(const float4*)&B[(size_t)(kb + bkk) * EE + j0 + bcol + 4];
        br[0]=v0.x; br[1]=v0.y; br[2]=v0.z; br[3]=v0.w;
        br[4]=v1.x; br[5]=v1.y; br[6]=v1.z; br[7]=v1.w;
    }

    u64 acc[8][4];
#pragma unroll
    for (int i = 0; i < 8; ++i)
#pragma unroll
        for (int j = 0; j < 4; ++j) acc[i][j] = 0ull;

    for (int t = 0; t < 8; ++t) {
        const int buf = t & 1;
#pragma unroll
        for (int q = 0; q < 4; ++q)
            As2[buf][(amk >> 1) * 128 + 2 * (amc + 16 * q) + (amk & 1)] = ar[q];
#pragma unroll
        for (int u = 0; u < 8; ++u)
            Bs2[buf][(bkk >> 1) * 256 + 2 * (bcol + u) + (bkk & 1)] = br[u];
        __syncthreads();

        if (t + 1 < 8) {
            const int kb = kc + (t + 1) * 16;
#pragma unroll
            for (int q = 0; q < 4; ++q) ar[q] = A[(size_t)(amc + 16 * q) * EE + kb + amk];
            float4 v0 = *(const float4*)&B[(size_t)(kb + bkk) * EE + j0 + bcol];
            float4 v1 = *(const float4*)&B[(size_t)(kb + bkk) * EE + j0 + bcol + 4];
            br[0]=v0.x; br[1]=v0.y; br[2]=v0.z; br[3]=v0.w;
            br[4]=v1.x; br[5]=v1.y; br[6]=v1.z; br[7]=v1.w;
        }

#pragma unroll
        for (int k2 = 0; k2 < 8; ++k2) {
            u64 a2[8], b2[4];
#pragma unroll
            for (int i = 0; i < 8; ++i)
                a2[i] = *(const u64*)&Bs2[buf][k2 * 256 + 2 * (ty + 16 * i)];
#pragma unroll
            for (int j = 0; j < 4; ++j)
                b2[j] = *(const u64*)&As2[buf][k2 * 128 + 2 * (tx + 16 * j)];
#pragma unroll
            for (int i = 0; i < 8; ++i)
#pragma unroll
                for (int j = 0; j < 4; ++j)
                    ffma2(acc[i][j], a2[i], b2[j]);
        }
        __syncthreads();
    }

#pragma unroll
    for (int i = 0; i < 8; ++i) {
        const int jg = j0 + ty + 16 * i;
#pragma unroll
        for (int jj = 0; jj < 4; ++jj) {
            const int c = tx + 16 * jj;
            float2 v = unpack2(acc[i][jj]);
            g_part[((size_t)blockIdx.y * CC + c) * EE + jg] = v.x + v.y;
        }
    }
}

// which==0: -> g_T1 (fp32).  which==1: scaled M -> bf16 hi/lo, pre-swizzled tiles.
__global__ void reduce16(float scale, int which)
{
    const int i = blockIdx.x * 256 + threadIdx.x;   // 0 .. 131071
    float s = 0.f;
#pragma unroll
    for (int q = 0; q < 16; ++q) s += g_part[(size_t)q * (CC * EE) + i];
    s *= scale;
    if (which == 0) {
        g_T1[i] = s;
    } else {
        __nv_bfloat16 h = __float2bfloat16(s);
        float hf = __bfloat162float(h);
        __nv_bfloat16 l = __float2bfloat16(s - hf);
        const int c = i >> 11, k = i & 2047;
        const int stage = k >> 6, kk = k & 63;
        u32 sw = swz((u32)(c * 128 + kk * 2));
        *(__nv_bfloat16*)(g_Bh + (size_t)stage * 8192 + sw) = h;
        *(__nv_bfloat16*)(g_Bl + (size_t)stage * 8192 + sw) = l;
    }
}

__global__ void k_u(const float* __restrict__ bv, const float* __restrict__ Wo,
                    const float* __restrict__ bo)
{
    const int w = (blockIdx.x * 256 + threadIdx.x) >> 5;
    const int lane = threadIdx.x & 31;
    const float* row = Wo + (size_t)w * EE;
    float s = 0.f;
    for (int j = lane; j < EE; j += 32) s += bv[j] * row[j];
#pragma unroll
    for (int o = 16; o; o >>= 1) s += __shfl_xor_sync(0xffffffffu, s, o);
    if (lane == 0) g_u[w] = s + bo[w];
}

__global__ void k_beta(const float* __restrict__ Wmp, const float* __restrict__ bmp)
{
    const int c = blockIdx.x;
    const int lane = threadIdx.x;
    const float* row = Wmp + (size_t)c * EE;
    float s = 0.f;
    for (int i = lane; i < EE; i += 32) s += g_u[i] * row[i];
#pragma unroll
    for (int o = 16; o; o >>= 1) s += __shfl_xor_sync(0xffffffffu, s, o);
    if (lane == 0) g_beta[c] = 0.75f * s + bmp[c];
}

// ---------------------------------------------------------------------------
// Main GEMM via mma.sync bf16 split:  out[n,c] = x[n,:] . M[c,:] + beta[c]
//   D += Ah*Bh + Ah*Bl + Al*Bh  (fp32 register accumulators)
// 144 CTAs x 256 threads (8 warps x m16). K in 32 chunks of 64, double-buffered.
// X converted fp32->bf16 hi/lo in-kernel; M hi/lo pre-swizzled, cp.async.
// Permuted [F,P]->[P,F] epilogue with beta.
// ---------------------------------------------------------------------------
__global__ void __launch_bounds__(256, 1)
main_mma(const float* __restrict__ x, float* __restrict__ out)
{
    extern __shared__ char smraw[];
    const u32 base = (smem_u32(smraw) + 1023u) & ~1023u;
    const u32 XH[2] = { base,          base + 16384u };
    const u32 XL[2] = { base + 32768u, base + 49152u };
    const u32 BH[2] = { base + 65536u, base + 73728u };
    const u32 BL[2] = { base + 81920u, base + 90112u };

    const int tid = threadIdx.x;
    const int wid = tid >> 5, lane = tid & 31;
    const int n0 = blockIdx.x * 128;
    const int m0 = wid * 16;

    float acc[8][4];
#pragma unroll
    for (int i = 0; i < 8; ++i)
#pragma unroll
        for (int j = 0; j < 4; ++j) acc[i][j] = 0.f;

    // X loader mapping: thread covers rows (tid>>4)+16i, float4-col (tid&15)
    const int xr = tid >> 4, xc4 = tid & 15;

    // prologue: chunk 0
    float4 ra[8];
#pragma unroll
    for (int i = 0; i < 8; ++i)
        ra[i] = *(const float4*)(x + (size_t)(n0 + xr + 16 * i) * EE + xc4 * 4);
    {
        const char* sh = (const char*)g_Bh + (size_t)tid * 32;
        const char* sl = (const char*)g_Bl + (size_t)tid * 32;
        cp16(BH[0] + (u32)tid * 32,      sh);
        cp16(BH[0] + (u32)tid * 32 + 16, sh + 16);
        cp16(BL[0] + (u32)tid * 32,      sl);
        cp16(BL[0] + (u32)tid * 32 + 16, sl + 16);
        cp_commit();
    }

    for (int t = 0; t < NSTG; ++t) {
        const int buf = t & 1;
        cp_wait0();   // B chunk t arrived

        // convert & store X chunk t (hi/lo, swizzled)
#pragma unroll
        for (int i = 0; i < 8; ++i) {
            const u32 sw = swz((u32)((xr + 16 * i) * 128 + xc4 * 8));
            float4 v = ra[i];
            u32 h01, h23, l01, l23;
            asm("cvt.rn.bf16x2.f32 %0, %1, %2;" : "=r"(h01) : "f"(v.y), "f"(v.x));
            asm("cvt.rn.bf16x2.f32 %0, %1, %2;" : "=r"(h23) : "f"(v.w), "f"(v.z));
            float e0 = v.x - __uint_as_float(h01 << 16);
            float e1 = v.y - __uint_as_float(h01 & 0xffff0000u);
            float e2 = v.z - __uint_as_float(h23 << 16);
            float e3 = v.w - __uint_as_float(h23 & 0xffff0000u);
            asm("cvt.rn.bf16x2.f32 %0, %1, %2;" : "=r"(l01) : "f"(e1), "f"(e0));
            asm("cvt.rn.bf16x2.f32 %0, %1, %2;" : "=r"(l23) : "f"(e3), "f"(e2));
            sts64(XH[buf] + sw, h01, h23);
            sts64(XL[buf] + sw, l01, l23);
        }
        __syncthreads();

        // issue next-chunk B cp.async + X LDG prefetch (overlap with MMA)
        if (t + 1 < NSTG) {
            const u32 nb = BH[buf ^ 1], nl = BL[buf ^ 1];
            const char* sh = (const char*)g_Bh + (size_t)(t + 1) * 8192 + tid * 32;
            const char* sl = (const char*)g_Bl + (size_t)(t + 1) * 8192 + tid * 32;
            cp16(nb + (u32)tid * 32,      sh);
            cp16(nb + (u32)tid * 32 + 16, sh + 16);
            cp16(nl + (u32)tid * 32,      sl);
            cp16(nl + (u32)tid * 32 + 16, sl + 16);
            cp_commit();
            const int k0 = (t + 1) * KS;
#pragma unroll
            for (int i = 0; i < 8; ++i)
                ra[i] = *(const float4*)(x + (size_t)(n0 + xr + 16 * i) * EE + k0 + xc4 * 4);
        }

        // MMA over chunk t
#pragma unroll
        for (int s = 0; s < 4; ++s) {
            const u32 xo = swz((u32)((m0 + (lane & 15)) * 128 + s * 32 + (lane >> 4) * 16));
            u32 a0, a1, a2, a3, f0, f1, f2, f3;
            ldsm4(a0, a1, a2, a3, XH[buf] + xo);
            ldsm4(f0, f1, f2, f3, XL[buf] + xo);
#pragma unroll
            for (int j = 0; j < 4; ++j) {
                const u32 bo = swz((u32)((16 * j + (lane & 15)) * 128 + s * 32 + (lane >> 4) * 16));
                u32 h0, h1, h2, h3, l0, l1, l2, l3;
                ldsm4(h0, h1, h2, h3, BH[buf] + bo);
                ldsm4(l0, l1, l2, l3, BL[buf] + bo);
                mma16816(acc[2 * j],     a0, a1, a2, a3, h0, h2);
                mma16816(acc[2 * j],     a0, a1, a2, a3, l0, l2);
                mma16816(acc[2 * j],     f0, f1, f2, f3, h0, h2);
                mma16816(acc[2 * j + 1], a0, a1, a2, a3, h1, h3);
                mma16816(acc[2 * j + 1], a0, a1, a2, a3, l1, l3);
                mma16816(acc[2 * j + 1], f0, f1, f2, f3, h1, h3);
            }
        }
    }

    // Epilogue: permuted store [F,P]->[P,F], + beta
    const int r0 = lane >> 2;          // 0..7
    const int cb = 2 * (lane & 3);     // 0,2,4,6
    const int na = n0 + m0 + r0;
    const int nb2 = na + 8;
    const int pa = na & 1023, ta = na >> 10;
    const int pb = nb2 & 1023, tb = nb2 >> 10;
    float* oa = out + (size_t)pa * (FF * CC) + ta * CC;
    float* ob = out + (size_t)pb * (FF * CC) + tb * CC;
#pragma unroll
    for (int nt = 0; nt < 8; ++nt) {
        const int c = 8 * nt + cb;
        const float2 b = *(const float2*)&g_beta[c];
        float2 w0, w1;
        w0.x = acc[nt][0] + b.x; w0.y = acc[nt][1] + b.y;
        w1.x = acc[nt][2] + b.x; w1.y = acc[nt][3] + b.y;
        *(float2*)(oa + c) = w0;
        *(float2*)(ob + c) = w1;
    }
}

// ---------------------------------------------------------------------------
extern "C" void kernel_launch(void* const* d_in, const int* in_sizes, int n_in,
                              void* d_out, int out_size)
{
    (void)in_sizes; (void)n_in; (void)out_size;
    const float* emb = (const float*)d_in[0];
    const float* Wv  = (const float*)d_in[3];
    const float* bv  = (const float*)d_in[6];
    const float* Wo  = (const float*)d_in[7];
    const float* bo  = (const float*)d_in[8];
    const float* Wmp = (const float*)d_in[9];
    const float* bmp = (const float*)d_in[10];
    float* out = (float*)d_out;

    // Fold weights: T1 = Wmp @ Wo ; M = 0.75 * T1 @ Wv (split bf16 hi/lo, pre-swizzled)
    gemm_nn_part<<<dim3(16, 16), 256>>>(Wmp, Wo, 0);
    reduce16<<<512, 256>>>(1.0f, 0);
    gemm_nn_part<<<dim3(16, 16), 256>>>(nullptr, Wv, 1);
    reduce16<<<512, 256>>>(0.75f, 1);

    // Fold biases: beta = 0.75*(bv@Wo^T + bo)@Wmp^T + bmp
    k_u<<<256, 256>>>(bv, Wo, bo);
    k_beta<<<64, 32>>>(Wmp, bmp);

    // Main GEMM (HMMA bf16 3-term split) + permuted epilogue
    const int smem_bytes = 98304 + 1024;
    cudaFuncSetAttribute(main_mma, cudaFuncAttributeMaxDynamicSharedMemorySize, smem_bytes);
    main_mma<<<144, 256, smem_bytes>>>(emb, out);
}